// round 12
// baseline (speedup 1.0000x reference)
#include <cuda_runtime.h>
#include <cuda_fp16.h>
#include <cstdint>

// ---------------- problem constants ----------------
#define NMAX 100000
#define EMAX 1600000
#define H    128
#define SCAN_CHUNK 512
#define NB_MAX 256

// ---------------- device scratch (no allocs allowed) ----------------
__device__ float  g_dinv[NMAX];
__device__ int    g_deg[NMAX];
__device__ int    g_rowptr[NMAX + 1];
__device__ int    g_cursor[NMAX];
__device__ int    g_bsums[NB_MAX];
__device__ uint2  g_csr[EMAX];                    // {src, bitcast fp32 dinv[src]}
__device__ __half g_hA[(size_t)NMAX * H];         // ping
__device__ __half g_hB[(size_t)NMAX * H];         // pong
__device__ __half g_cath[(size_t)NMAX * 3 * H];   // fp16 JK concat, ld=384

// ---------------- mma / ldmatrix helpers ----------------
__device__ __forceinline__ uint32_t smem_u32(const void* p) {
    return (uint32_t)__cvta_generic_to_shared(p);
}

__device__ __forceinline__ void ldsm_x4(uint32_t* r, uint32_t addr) {
    asm volatile("ldmatrix.sync.aligned.m8n8.x4.shared.b16 {%0,%1,%2,%3}, [%4];"
        : "=r"(r[0]), "=r"(r[1]), "=r"(r[2]), "=r"(r[3]) : "r"(addr));
}

__device__ __forceinline__ void ldsm_x4_t(uint32_t* r, uint32_t addr) {
    asm volatile("ldmatrix.sync.aligned.m8n8.x4.trans.shared.b16 {%0,%1,%2,%3}, [%4];"
        : "=r"(r[0]), "=r"(r[1]), "=r"(r[2]), "=r"(r[3]) : "r"(addr));
}

__device__ __forceinline__ void mma_f16(float* d, const uint32_t* a, const uint32_t* b) {
    asm volatile(
        "mma.sync.aligned.m16n8k16.row.col.f32.f16.f16.f32 "
        "{%0,%1,%2,%3}, {%4,%5,%6,%7}, {%8,%9}, {%0,%1,%2,%3};"
        : "+f"(d[0]), "+f"(d[1]), "+f"(d[2]), "+f"(d[3])
        : "r"(a[0]), "r"(a[1]), "r"(a[2]), "r"(a[3]), "r"(b[0]), "r"(b[1]));
}

__device__ __forceinline__ uint32_t pack_h2(float x, float y) {
    __half2 h = __floats2half2_rn(x, y);
    return *(uint32_t*)&h;
}

// ---------------- CSR build ----------------
__global__ void k_hist(int* __restrict__ deg, const int* __restrict__ ei, int E) {
    int e = blockIdx.x * blockDim.x + threadIdx.x;
    if (e < E) atomicAdd(&deg[ei[E + e]], 1);
}

__global__ void __launch_bounds__(SCAN_CHUNK) k_scan1(
    const int* __restrict__ deg, int* __restrict__ bsums,
    float* __restrict__ dinv, int N)
{
    __shared__ int s[SCAN_CHUNK];
    int t = threadIdx.x;
    int i = blockIdx.x * SCAN_CHUNK + t;
    int v = (i < N) ? deg[i] : 0;
    if (i < N) dinv[i] = rsqrtf(1.0f + (float)v);
    s[t] = v;
    __syncthreads();
    for (int off = SCAN_CHUNK / 2; off > 0; off >>= 1) {
        if (t < off) s[t] += s[t + off];
        __syncthreads();
    }
    if (t == 0) bsums[blockIdx.x] = s[0];
}

__global__ void __launch_bounds__(NB_MAX) k_scan2(
    int* __restrict__ bsums, int* __restrict__ rowptr, int NB, int N)
{
    __shared__ int s[NB_MAX];
    int t = threadIdx.x;
    int v = (t < NB) ? bsums[t] : 0;
    s[t] = v;
    __syncthreads();
    for (int off = 1; off < NB_MAX; off <<= 1) {
        int x = (t >= off) ? s[t - off] : 0;
        __syncthreads();
        s[t] += x;
        __syncthreads();
    }
    if (t < NB) bsums[t] = s[t] - v;
    if (t == NB_MAX - 1) rowptr[N] = s[NB_MAX - 1];
}

__global__ void __launch_bounds__(SCAN_CHUNK) k_scan3(
    const int* __restrict__ deg, const int* __restrict__ bsums,
    int* __restrict__ rowptr, int* __restrict__ cursor, int N)
{
    __shared__ int s[SCAN_CHUNK];
    int t = threadIdx.x;
    int i = blockIdx.x * SCAN_CHUNK + t;
    int v = (i < N) ? deg[i] : 0;
    s[t] = v;
    __syncthreads();
    for (int off = 1; off < SCAN_CHUNK; off <<= 1) {
        int x = (t >= off) ? s[t - off] : 0;
        __syncthreads();
        s[t] += x;
        __syncthreads();
    }
    if (i < N) {
        int excl = s[t] - v + bsums[blockIdx.x];
        rowptr[i] = excl;
        cursor[i] = excl;
    }
}

__global__ void k_fill(const int* __restrict__ ei,
                       const float* __restrict__ dinv,
                       int* __restrict__ cursor,
                       uint2* __restrict__ csr, int E)
{
    int e = blockIdx.x * blockDim.x + threadIdx.x;
    if (e >= E) return;
    int r = ei[e];
    int c = ei[E + e];
    int pos = atomicAdd(&cursor[c], 1);
    csr[pos] = make_uint2((uint32_t)r, __float_as_uint(dinv[r]));
}

// ---------------- aggregate core: one warp, one node -> acc[8] ----------------
__device__ __forceinline__ void agg_node(
    int n, float dv, int beg, int end,
    const uint2* __restrict__ csr,
    const __half* __restrict__ hWh,
    int half, int hl, float* acc)
{
#pragma unroll
    for (int f = 0; f < 8; f++) acc[f] = 0.f;
    int i = beg;
    for (; i + 4 <= end; i += 4) {
        uint2 m0 = csr[i +     half];
        uint2 m1 = csr[i + 2 + half];
        float w0 = __uint_as_float(m0.y) * dv;
        float w1 = __uint_as_float(m1.y) * dv;
        uint4 u0 = ((const uint4*)(hWh + (size_t)m0.x * H))[hl];
        uint4 u1 = ((const uint4*)(hWh + (size_t)m1.x * H))[hl];
        float2 p;
        p = __half22float2(*(__half2*)&u0.x); acc[0] += p.x*w0; acc[1] += p.y*w0;
        p = __half22float2(*(__half2*)&u0.y); acc[2] += p.x*w0; acc[3] += p.y*w0;
        p = __half22float2(*(__half2*)&u0.z); acc[4] += p.x*w0; acc[5] += p.y*w0;
        p = __half22float2(*(__half2*)&u0.w); acc[6] += p.x*w0; acc[7] += p.y*w0;
        p = __half22float2(*(__half2*)&u1.x); acc[0] += p.x*w1; acc[1] += p.y*w1;
        p = __half22float2(*(__half2*)&u1.y); acc[2] += p.x*w1; acc[3] += p.y*w1;
        p = __half22float2(*(__half2*)&u1.z); acc[4] += p.x*w1; acc[5] += p.y*w1;
        p = __half22float2(*(__half2*)&u1.w); acc[6] += p.x*w1; acc[7] += p.y*w1;
    }
    for (; i < end; i += 2) {
        int e = i + half;
        uint32_t r = (uint32_t)n;
        float w = 0.f;
        if (e < end) { uint2 m = csr[e]; r = m.x; w = __uint_as_float(m.y) * dv; }
        uint4 u = ((const uint4*)(hWh + (size_t)r * H))[hl];
        float2 p;
        p = __half22float2(*(__half2*)&u.x); acc[0] += p.x*w; acc[1] += p.y*w;
        p = __half22float2(*(__half2*)&u.y); acc[2] += p.x*w; acc[3] += p.y*w;
        p = __half22float2(*(__half2*)&u.z); acc[4] += p.x*w; acc[5] += p.y*w;
        p = __half22float2(*(__half2*)&u.w); acc[6] += p.x*w; acc[7] += p.y*w;
    }
#pragma unroll
    for (int f = 0; f < 8; f++)
        acc[f] += __shfl_xor_sync(0xffffffffu, acc[f], 16);
}

__device__ __forceinline__ uint4 agg_epilogue(
    int n, float dv, const __half* __restrict__ hWh,
    const float* __restrict__ bias, int hl, float* acc)
{
    float sn = dv * dv;
    uint4 us = ((const uint4*)(hWh + (size_t)n * H))[hl];
    float2 p;
    p = __half22float2(*(__half2*)&us.x); acc[0] += p.x*sn; acc[1] += p.y*sn;
    p = __half22float2(*(__half2*)&us.y); acc[2] += p.x*sn; acc[3] += p.y*sn;
    p = __half22float2(*(__half2*)&us.z); acc[4] += p.x*sn; acc[5] += p.y*sn;
    p = __half22float2(*(__half2*)&us.w); acc[6] += p.x*sn; acc[7] += p.y*sn;
    float4 b0 = ((const float4*)bias)[hl * 2];
    float4 b1 = ((const float4*)bias)[hl * 2 + 1];
    uint4 o;
    o.x = pack_h2(fmaxf(acc[0] + b0.x, 0.f), fmaxf(acc[1] + b0.y, 0.f));
    o.y = pack_h2(fmaxf(acc[2] + b0.z, 0.f), fmaxf(acc[3] + b0.w, 0.f));
    o.z = pack_h2(fmaxf(acc[4] + b1.x, 0.f), fmaxf(acc[5] + b1.y, 0.f));
    o.w = pack_h2(fmaxf(acc[6] + b1.z, 0.f), fmaxf(acc[7] + b1.w, 0.f));
    return o;
}

// ---------------- layer-1 conv GEMM (fp32 in): hWh = fp16(X @ W) ----------------
__global__ void __launch_bounds__(256) k_conv_gemm(
    const float* __restrict__ X, int ldx,
    const float* __restrict__ W,
    __half* __restrict__ hWh, int N)
{
    __shared__ __half Xs[128][88];
    __shared__ __half Ws[64][136];

    const int tid  = threadIdx.x;
    const int lane = tid & 31;
    const int warp = tid >> 5;
    const int wm   = warp >> 2;
    const int wn   = warp & 3;
    const int row0 = blockIdx.x * 128;

    const int g  = lane >> 2;
    const int tg = lane & 3;

    float acc[4][4][4];
#pragma unroll
    for (int i = 0; i < 4; i++)
#pragma unroll
        for (int j = 0; j < 4; j++)
#pragma unroll
            for (int q = 0; q < 4; q++) acc[i][j][q] = 0.f;

    const int a_row = lane & 15;
    const int a_kof = (lane >> 4) * 8;
    const int b_krow = lane & 15;
    const int b_cof  = (lane >> 4) * 8;

    for (int kc = 0; kc < 128; kc += 64) {
        __syncthreads();
#pragma unroll
        for (int i = tid; i < 2048; i += 256) {
            int k = i >> 5, c4 = i & 31;
            float4 v = ((const float4*)(W + (size_t)(kc + k) * 128))[c4];
            uint2 p = make_uint2(pack_h2(v.x, v.y), pack_h2(v.z, v.w));
            *(uint2*)&Ws[k][c4 * 4] = p;
        }
#pragma unroll
        for (int i = tid; i < 2048; i += 256) {
            int r = i >> 4, c4 = i & 15;
            int gr = row0 + r;
            float4 v = make_float4(0.f, 0.f, 0.f, 0.f);
            if (gr < N) v = *(const float4*)(X + (size_t)gr * ldx + kc + c4 * 4);
            uint2 p = make_uint2(pack_h2(v.x, v.y), pack_h2(v.z, v.w));
            *(uint2*)&Xs[r][c4 * 4] = p;
        }
        __syncthreads();

#pragma unroll
        for (int kk = 0; kk < 4; kk++) {
            const int k0 = kk * 16;
            uint32_t a[4][4], b[4][2];
#pragma unroll
            for (int i = 0; i < 4; i++) {
                uint32_t ad = smem_u32(&Xs[wm * 64 + i * 16 + a_row][k0 + a_kof]);
                ldsm_x4(a[i], ad);
            }
#pragma unroll
            for (int jp = 0; jp < 2; jp++) {
                uint32_t r4[4];
                uint32_t ad = smem_u32(&Ws[k0 + b_krow][wn * 32 + jp * 16 + b_cof]);
                ldsm_x4_t(r4, ad);
                b[jp * 2    ][0] = r4[0]; b[jp * 2    ][1] = r4[1];
                b[jp * 2 + 1][0] = r4[2]; b[jp * 2 + 1][1] = r4[3];
            }
#pragma unroll
            for (int i = 0; i < 4; i++)
#pragma unroll
                for (int j = 0; j < 4; j++)
                    mma_f16(acc[i][j], a[i], b[j]);
        }
    }

#pragma unroll
    for (int i = 0; i < 4; i++) {
        int r = row0 + wm * 64 + i * 16 + g;
#pragma unroll
        for (int j = 0; j < 4; j++) {
            int c = wn * 32 + j * 8 + 2 * tg;
            if (r < N)
                *(uint32_t*)(hWh + (size_t)r * H + c) = pack_h2(acc[i][j][0], acc[i][j][1]);
            if (r + 8 < N)
                *(uint32_t*)(hWh + (size_t)(r + 8) * H + c) = pack_h2(acc[i][j][2], acc[i][j][3]);
        }
    }
}

// ---------------- FUSED: aggregate(hin,bias)->cath slice + smem; GEMM @W -> hout ----------------
// Block = 128 nodes. Dynamic smem: Xs[128][136] + Ws[128][136] halves (68 KB).
__global__ void __launch_bounds__(256, 2) k_agg_gemm(
    const int* __restrict__ rowptr,
    const uint2* __restrict__ csr,
    const float* __restrict__ dinv,
    const __half* __restrict__ hin,
    const float* __restrict__ bias,    // bias of PREVIOUS conv layer
    const float* __restrict__ W,       // [128,128] fp32, THIS layer
    __half* __restrict__ cath,         // + slice offset applied by caller
    __half* __restrict__ hout, int N)
{
    extern __shared__ __half sm[];
    __half (*Xs)[136] = (__half(*)[136])sm;
    __half (*Ws)[136] = (__half(*)[136])(sm + 128 * 136);

    const int tid  = threadIdx.x;
    const int lane = tid & 31;
    const int warp = tid >> 5;
    const int row0 = blockIdx.x * 128;
    const int half = lane >> 4;
    const int hl   = lane & 15;

    // stage W fully (128x128 fp32 -> fp16)
#pragma unroll
    for (int i = tid; i < 4096; i += 256) {
        int k = i >> 5, c4 = i & 31;
        float4 v = ((const float4*)(W + (size_t)k * 128))[c4];
        uint2 p = make_uint2(pack_h2(v.x, v.y), pack_h2(v.z, v.w));
        *(uint2*)&Ws[k][c4 * 4] = p;
    }

    // aggregate phase: each warp does 16 nodes
    for (int it = 0; it < 16; it++) {
        int nl = warp * 16 + it;
        int n  = row0 + nl;
        if (n < N) {
            float dv = dinv[n];
            float acc[8];
            agg_node(n, dv, rowptr[n], rowptr[n + 1], csr, hin, half, hl, acc);
            if (half == 0) {
                uint4 o = agg_epilogue(n, dv, hin, bias, hl, acc);
                *(uint4*)(cath + (size_t)n * 384 + hl * 8) = o;
                *(uint4*)&Xs[nl][hl * 8] = o;
            }
        } else if (half == 0) {
            *(uint4*)&Xs[nl][hl * 8] = make_uint4(0u, 0u, 0u, 0u);
        }
    }
    __syncthreads();

    // GEMM phase: Xs[128x128] @ Ws -> hout
    const int wm = warp >> 2;
    const int wn = warp & 3;
    const int g  = lane >> 2;
    const int tg = lane & 3;
    const int a_row = lane & 15;
    const int a_kof = (lane >> 4) * 8;
    const int b_krow = lane & 15;
    const int b_cof  = (lane >> 4) * 8;

    float acc[4][4][4];
#pragma unroll
    for (int i = 0; i < 4; i++)
#pragma unroll
        for (int j = 0; j < 4; j++)
#pragma unroll
            for (int q = 0; q < 4; q++) acc[i][j][q] = 0.f;

#pragma unroll
    for (int kk = 0; kk < 8; kk++) {
        const int k0 = kk * 16;
        uint32_t a[4][4], b[4][2];
#pragma unroll
        for (int i = 0; i < 4; i++) {
            uint32_t ad = smem_u32(&Xs[wm * 64 + i * 16 + a_row][k0 + a_kof]);
            ldsm_x4(a[i], ad);
        }
#pragma unroll
        for (int jp = 0; jp < 2; jp++) {
            uint32_t r4[4];
            uint32_t ad = smem_u32(&Ws[k0 + b_krow][wn * 32 + jp * 16 + b_cof]);
            ldsm_x4_t(r4, ad);
            b[jp * 2    ][0] = r4[0]; b[jp * 2    ][1] = r4[1];
            b[jp * 2 + 1][0] = r4[2]; b[jp * 2 + 1][1] = r4[3];
        }
#pragma unroll
        for (int i = 0; i < 4; i++)
#pragma unroll
            for (int j = 0; j < 4; j++)
                mma_f16(acc[i][j], a[i], b[j]);
    }

#pragma unroll
    for (int i = 0; i < 4; i++) {
        int r = row0 + wm * 64 + i * 16 + g;
#pragma unroll
        for (int j = 0; j < 4; j++) {
            int c = wn * 32 + j * 8 + 2 * tg;
            if (r < N)
                *(uint32_t*)(hout + (size_t)r * H + c) = pack_h2(acc[i][j][0], acc[i][j][1]);
            if (r + 8 < N)
                *(uint32_t*)(hout + (size_t)(r + 8) * H + c) = pack_h2(acc[i][j][2], acc[i][j][3]);
        }
    }
}

// ---------------- standalone aggregate (layer 3) ----------------
__global__ void __launch_bounds__(256) k_aggregate(
    const int* __restrict__ rowptr,
    const uint2* __restrict__ csr,
    const float* __restrict__ dinv,
    const __half* __restrict__ hWh,
    const float* __restrict__ bias,
    __half* __restrict__ cath, int off, int N)
{
    int n = blockIdx.x * 8 + (threadIdx.x >> 5);
    if (n >= N) return;
    const int lane = threadIdx.x & 31;
    const int half = lane >> 4;
    const int hl   = lane & 15;

    float dv = dinv[n];
    float acc[8];
    agg_node(n, dv, rowptr[n], rowptr[n + 1], csr, hWh, half, hl, acc);
    if (half == 0) {
        uint4 o = agg_epilogue(n, dv, hWh, bias, hl, acc);
        *(uint4*)(cath + (size_t)n * 384 + off + hl * 8) = o;
    }
}

// ---------------- final GEMM (fp16 mma): out = cat[N,384] @ Wlin[384,64] + blin ----------------
__global__ void __launch_bounds__(256) k_final_gemm(
    const __half* __restrict__ cath,
    const float* __restrict__ W,
    const float* __restrict__ bias,
    float* __restrict__ out, int N)
{
    __shared__ __half Xs[128][88];
    __shared__ __half Ws[64][72];

    const int tid  = threadIdx.x;
    const int lane = tid & 31;
    const int warp = tid >> 5;
    const int wm   = warp & 3;
    const int wn   = warp >> 2;
    const int row0 = blockIdx.x * 128;

    const int g  = lane >> 2;
    const int tg = lane & 3;

    float acc[2][4][4];
#pragma unroll
    for (int i = 0; i < 2; i++)
#pragma unroll
        for (int j = 0; j < 4; j++)
#pragma unroll
            for (int q = 0; q < 4; q++) acc[i][j][q] = 0.f;

    const int a_row = lane & 15;
    const int a_kof = (lane >> 4) * 8;
    const int b_krow = lane & 15;
    const int b_cof  = (lane >> 4) * 8;

    for (int kc = 0; kc < 384; kc += 64) {
        __syncthreads();
#pragma unroll
        for (int i = tid; i < 1024; i += 256) {
            int k = i >> 4, c4 = i & 15;
            float4 v = ((const float4*)(W + (size_t)(kc + k) * 64))[c4];
            uint2 p = make_uint2(pack_h2(v.x, v.y), pack_h2(v.z, v.w));
            *(uint2*)&Ws[k][c4 * 4] = p;
        }
#pragma unroll
        for (int i = tid; i < 1024; i += 256) {
            int r = i >> 3, c = i & 7;
            int gr = row0 + r;
            uint4 v = make_uint4(0u, 0u, 0u, 0u);
            if (gr < N) v = *(const uint4*)(cath + (size_t)gr * 384 + kc + c * 8);
            *(uint4*)&Xs[r][c * 8] = v;
        }
        __syncthreads();

#pragma unroll
        for (int kk = 0; kk < 4; kk++) {
            const int k0 = kk * 16;
            uint32_t a[2][4], b[4][2];
#pragma unroll
            for (int i = 0; i < 2; i++) {
                uint32_t ad = smem_u32(&Xs[wm * 32 + i * 16 + a_row][k0 + a_kof]);
                ldsm_x4(a[i], ad);
            }
#pragma unroll
            for (int jp = 0; jp < 2; jp++) {
                uint32_t r4[4];
                uint32_t ad = smem_u32(&Ws[k0 + b_krow][wn * 32 + jp * 16 + b_cof]);
                ldsm_x4_t(r4, ad);
                b[jp * 2    ][0] = r4[0]; b[jp * 2    ][1] = r4[1];
                b[jp * 2 + 1][0] = r4[2]; b[jp * 2 + 1][1] = r4[3];
            }
#pragma unroll
            for (int i = 0; i < 2; i++)
#pragma unroll
                for (int j = 0; j < 4; j++)
                    mma_f16(acc[i][j], a[i], b[j]);
        }
    }

#pragma unroll
    for (int i = 0; i < 2; i++) {
        int r = row0 + wm * 32 + i * 16 + g;
#pragma unroll
        for (int j = 0; j < 4; j++) {
            int c = wn * 32 + j * 8 + 2 * tg;
            float b0 = bias[c], b1 = bias[c + 1];
            if (r < N)
                *(float2*)(out + (size_t)r * 64 + c) =
                    make_float2(acc[i][j][0] + b0, acc[i][j][1] + b1);
            if (r + 8 < N)
                *(float2*)(out + (size_t)(r + 8) * 64 + c) =
                    make_float2(acc[i][j][2] + b0, acc[i][j][3] + b1);
        }
    }
}

// ---------------- launch ----------------
extern "C" void kernel_launch(void* const* d_in, const int* in_sizes, int n_in,
                              void* d_out, int out_size)
{
    const float* x    = (const float*)d_in[0];
    const int*   ei   = (const int*)d_in[1];      // int32 (JAX x64 disabled)
    const float* W1   = (const float*)d_in[2];
    const float* b1   = (const float*)d_in[3];
    const float* W2   = (const float*)d_in[4];
    const float* b2   = (const float*)d_in[5];
    const float* W3   = (const float*)d_in[6];
    const float* b3   = (const float*)d_in[7];
    const float* Wlin = (const float*)d_in[8];
    const float* blin = (const float*)d_in[9];
    float* out = (float*)d_out;

    float *dinv;
    __half *hA, *hB, *cath;
    uint2 *csr;
    int *deg, *rowptr, *cursor, *bsums;
    cudaGetSymbolAddress((void**)&dinv,   g_dinv);
    cudaGetSymbolAddress((void**)&deg,    g_deg);
    cudaGetSymbolAddress((void**)&rowptr, g_rowptr);
    cudaGetSymbolAddress((void**)&cursor, g_cursor);
    cudaGetSymbolAddress((void**)&bsums,  g_bsums);
    cudaGetSymbolAddress((void**)&csr,    g_csr);
    cudaGetSymbolAddress((void**)&hA,     g_hA);
    cudaGetSymbolAddress((void**)&hB,     g_hB);
    cudaGetSymbolAddress((void**)&cath,   g_cath);

    const int N = in_sizes[0] / H;      // 100000
    const int E = in_sizes[1] / 2;      // 1600000
    const int NB = (N + SCAN_CHUNK - 1) / SCAN_CHUNK;

    const int T = 256;
    const int gE    = (E + T - 1) / T;
    const int gGemm = (N + 127) / 128;
    const int gAgg  = (N + 7) / 8;
    const int FUSED_SMEM = 2 * 128 * 136 * (int)sizeof(__half);   // 69632 B

    cudaFuncSetAttribute(k_agg_gemm,
                         cudaFuncAttributeMaxDynamicSharedMemorySize, FUSED_SMEM);

    // layer-1 GEMM (independent of CSR build)
    k_conv_gemm<<<gGemm, T>>>(x, H, W1, hA, N);

    // CSR build
    cudaMemsetAsync(deg, 0, (size_t)N * sizeof(int));
    k_hist <<<gE, T>>>(deg, ei, E);
    k_scan1<<<NB, SCAN_CHUNK>>>(deg, bsums, dinv, N);
    k_scan2<<<1, NB_MAX>>>(bsums, rowptr, NB, N);
    k_scan3<<<NB, SCAN_CHUNK>>>(deg, bsums, rowptr, cursor, N);
    k_fill <<<gE, T>>>(ei, dinv, cursor, csr, E);

    // fused agg1 + gemm2:  h1 = relu(agg(hA)+b1) -> cath slice0 ; hB = h1 @ W2
    k_agg_gemm<<<gGemm, T, FUSED_SMEM>>>(rowptr, csr, dinv, hA, b1, W2, cath, hB, N);

    // fused agg2 + gemm3:  h2 -> cath slice1 ; hA = h2 @ W3
    k_agg_gemm<<<gGemm, T, FUSED_SMEM>>>(rowptr, csr, dinv, hB, b2, W3, cath + 128, hA, N);

    // agg3 -> cath slice2
    k_aggregate<<<gAgg, T>>>(rowptr, csr, dinv, hA, b3, cath, 256, N);

    // final
    k_final_gemm<<<gGemm, T>>>(cath, Wlin, blin, out, N);
}

// round 13
// speedup vs baseline: 1.2311x; 1.2311x over previous
#include <cuda_runtime.h>
#include <cuda_fp16.h>
#include <cstdint>

// ---------------- problem constants ----------------
#define NMAX 100000
#define EMAX 1600000
#define H    128
#define SCAN_CHUNK 512
#define NB_MAX 256

// ---------------- device scratch (no allocs allowed) ----------------
__device__ float  g_dinv[NMAX];
__device__ int    g_deg[NMAX];
__device__ int    g_rowptr[NMAX + 1];
__device__ int    g_cursor[NMAX];
__device__ int    g_bsums[NB_MAX];
__device__ int    g_csr_src[EMAX];
__device__ float  g_csr_w[EMAX];
__device__ __half g_hWh [(size_t)NMAX * H];       // fp16 GEMM output
__device__ __half g_cath[(size_t)NMAX * 3 * H];   // fp16 JK concat, ld=384

// ---------------- mma / ldmatrix helpers ----------------
__device__ __forceinline__ uint32_t smem_u32(const void* p) {
    return (uint32_t)__cvta_generic_to_shared(p);
}

__device__ __forceinline__ void ldsm_x4(uint32_t* r, uint32_t addr) {
    asm volatile("ldmatrix.sync.aligned.m8n8.x4.shared.b16 {%0,%1,%2,%3}, [%4];"
        : "=r"(r[0]), "=r"(r[1]), "=r"(r[2]), "=r"(r[3]) : "r"(addr));
}

__device__ __forceinline__ void ldsm_x4_t(uint32_t* r, uint32_t addr) {
    asm volatile("ldmatrix.sync.aligned.m8n8.x4.trans.shared.b16 {%0,%1,%2,%3}, [%4];"
        : "=r"(r[0]), "=r"(r[1]), "=r"(r[2]), "=r"(r[3]) : "r"(addr));
}

__device__ __forceinline__ void mma_f16(float* d, const uint32_t* a, const uint32_t* b) {
    asm volatile(
        "mma.sync.aligned.m16n8k16.row.col.f32.f16.f16.f32 "
        "{%0,%1,%2,%3}, {%4,%5,%6,%7}, {%8,%9}, {%0,%1,%2,%3};"
        : "+f"(d[0]), "+f"(d[1]), "+f"(d[2]), "+f"(d[3])
        : "r"(a[0]), "r"(a[1]), "r"(a[2]), "r"(a[3]), "r"(b[0]), "r"(b[1]));
}

__device__ __forceinline__ uint32_t pack_h2(float x, float y) {
    __half2 h = __floats2half2_rn(x, y);
    return *(uint32_t*)&h;
}

// ---------------- CSR build ----------------
__global__ void k_hist(int* __restrict__ deg, const int* __restrict__ ei, int E) {
    int e = blockIdx.x * blockDim.x + threadIdx.x;
    if (e < E) atomicAdd(&deg[ei[E + e]], 1);
}

// scan stage 1 + dinv fused
__global__ void __launch_bounds__(SCAN_CHUNK) k_scan1(
    const int* __restrict__ deg, int* __restrict__ bsums,
    float* __restrict__ dinv, int N)
{
    __shared__ int s[SCAN_CHUNK];
    int t = threadIdx.x;
    int i = blockIdx.x * SCAN_CHUNK + t;
    int v = (i < N) ? deg[i] : 0;
    if (i < N) dinv[i] = rsqrtf(1.0f + (float)v);
    s[t] = v;
    __syncthreads();
    for (int off = SCAN_CHUNK / 2; off > 0; off >>= 1) {
        if (t < off) s[t] += s[t + off];
        __syncthreads();
    }
    if (t == 0) bsums[blockIdx.x] = s[0];
}

__global__ void __launch_bounds__(NB_MAX) k_scan2(
    int* __restrict__ bsums, int* __restrict__ rowptr, int NB, int N)
{
    __shared__ int s[NB_MAX];
    int t = threadIdx.x;
    int v = (t < NB) ? bsums[t] : 0;
    s[t] = v;
    __syncthreads();
    for (int off = 1; off < NB_MAX; off <<= 1) {
        int x = (t >= off) ? s[t - off] : 0;
        __syncthreads();
        s[t] += x;
        __syncthreads();
    }
    if (t < NB) bsums[t] = s[t] - v;
    if (t == NB_MAX - 1) rowptr[N] = s[NB_MAX - 1];
}

__global__ void __launch_bounds__(SCAN_CHUNK) k_scan3(
    const int* __restrict__ deg, const int* __restrict__ bsums,
    int* __restrict__ rowptr, int* __restrict__ cursor, int N)
{
    __shared__ int s[SCAN_CHUNK];
    int t = threadIdx.x;
    int i = blockIdx.x * SCAN_CHUNK + t;
    int v = (i < N) ? deg[i] : 0;
    s[t] = v;
    __syncthreads();
    for (int off = 1; off < SCAN_CHUNK; off <<= 1) {
        int x = (t >= off) ? s[t - off] : 0;
        __syncthreads();
        s[t] += x;
        __syncthreads();
    }
    if (i < N) {
        int excl = s[t] - v + bsums[blockIdx.x];
        rowptr[i] = excl;
        cursor[i] = excl;
    }
}

__global__ void k_fill(const int* __restrict__ ei,
                       const float* __restrict__ dinv,
                       int* __restrict__ cursor,
                       int* __restrict__ csr_src,
                       float* __restrict__ csr_w, int E)
{
    int e = blockIdx.x * blockDim.x + threadIdx.x;
    if (e >= E) return;
    int r = ei[e];
    int c = ei[E + e];
    int pos = atomicAdd(&cursor[c], 1);
    csr_src[pos] = r;
    csr_w[pos]   = dinv[r];
}

// ---------------- conv GEMM (fp16 mma): hWh = fp16(X @ W) ----------------
// Block 128x128, 8 warps (2x4), warp 64x32, K chunks of 64, m16n8k16.
template <bool FP16IN>
__global__ void __launch_bounds__(256) k_conv_gemm(
    const void* __restrict__ Xv, int ldx,
    const float* __restrict__ W,
    __half* __restrict__ hWh, int N)
{
    __shared__ __half Xs[128][88];
    __shared__ __half Ws[64][136];

    const int tid  = threadIdx.x;
    const int lane = tid & 31;
    const int warp = tid >> 5;
    const int wm   = warp >> 2;
    const int wn   = warp & 3;
    const int row0 = blockIdx.x * 128;

    const int g  = lane >> 2;
    const int tg = lane & 3;

    float acc[4][4][4];
#pragma unroll
    for (int i = 0; i < 4; i++)
#pragma unroll
        for (int j = 0; j < 4; j++)
#pragma unroll
            for (int q = 0; q < 4; q++) acc[i][j][q] = 0.f;

    const int a_row = lane & 15;
    const int a_kof = (lane >> 4) * 8;
    const int b_krow = lane & 15;
    const int b_cof  = (lane >> 4) * 8;

    for (int kc = 0; kc < 128; kc += 64) {
        __syncthreads();
#pragma unroll
        for (int i = tid; i < 2048; i += 256) {
            int k = i >> 5, c4 = i & 31;
            float4 v = ((const float4*)(W + (size_t)(kc + k) * 128))[c4];
            uint2 p = make_uint2(pack_h2(v.x, v.y), pack_h2(v.z, v.w));
            *(uint2*)&Ws[k][c4 * 4] = p;
        }
        if (FP16IN) {
            const __half* X = (const __half*)Xv;
#pragma unroll
            for (int i = tid; i < 1024; i += 256) {
                int r = i >> 3, c = i & 7;
                int gr = row0 + r;
                uint4 v = make_uint4(0u, 0u, 0u, 0u);
                if (gr < N) v = *(const uint4*)(X + (size_t)gr * ldx + kc + c * 8);
                *(uint4*)&Xs[r][c * 8] = v;
            }
        } else {
            const float* X = (const float*)Xv;
#pragma unroll
            for (int i = tid; i < 2048; i += 256) {
                int r = i >> 4, c4 = i & 15;
                int gr = row0 + r;
                float4 v = make_float4(0.f, 0.f, 0.f, 0.f);
                if (gr < N) v = *(const float4*)(X + (size_t)gr * ldx + kc + c4 * 4);
                uint2 p = make_uint2(pack_h2(v.x, v.y), pack_h2(v.z, v.w));
                *(uint2*)&Xs[r][c4 * 4] = p;
            }
        }
        __syncthreads();

#pragma unroll
        for (int kk = 0; kk < 4; kk++) {
            const int k0 = kk * 16;
            uint32_t a[4][4], b[4][2];
#pragma unroll
            for (int i = 0; i < 4; i++) {
                uint32_t ad = smem_u32(&Xs[wm * 64 + i * 16 + a_row][k0 + a_kof]);
                ldsm_x4(a[i], ad);
            }
#pragma unroll
            for (int jp = 0; jp < 2; jp++) {
                uint32_t r4[4];
                uint32_t ad = smem_u32(&Ws[k0 + b_krow][wn * 32 + jp * 16 + b_cof]);
                ldsm_x4_t(r4, ad);
                b[jp * 2    ][0] = r4[0]; b[jp * 2    ][1] = r4[1];
                b[jp * 2 + 1][0] = r4[2]; b[jp * 2 + 1][1] = r4[3];
            }
#pragma unroll
            for (int i = 0; i < 4; i++)
#pragma unroll
                for (int j = 0; j < 4; j++)
                    mma_f16(acc[i][j], a[i], b[j]);
        }
    }

#pragma unroll
    for (int i = 0; i < 4; i++) {
        int r = row0 + wm * 64 + i * 16 + g;
#pragma unroll
        for (int j = 0; j < 4; j++) {
            int c = wn * 32 + j * 8 + 2 * tg;
            if (r < N)
                *(uint32_t*)(hWh + (size_t)r * H + c) = pack_h2(acc[i][j][0], acc[i][j][1]);
            if (r + 8 < N)
                *(uint32_t*)(hWh + (size_t)(r + 8) * H + c) = pack_h2(acc[i][j][2], acc[i][j][3]);
        }
    }
}

// ---------------- fused aggregate: half-warp per edge, uint4 gathers -> fp16 cat ----------------
__global__ void __launch_bounds__(256) k_aggregate(
    const int* __restrict__ rowptr,
    const int* __restrict__ csr_src,
    const float* __restrict__ csr_w,
    const float* __restrict__ dinv,
    const __half* __restrict__ hWh,
    const float* __restrict__ bias,
    __half* __restrict__ cath, int off, int N)
{
    int n = blockIdx.x * 8 + (threadIdx.x >> 5);
    if (n >= N) return;
    const int lane = threadIdx.x & 31;
    const int half = lane >> 4;
    const int hl   = lane & 15;

    float dv = dinv[n];
    float acc[8];
#pragma unroll
    for (int f = 0; f < 8; f++) acc[f] = 0.f;

    const int beg = rowptr[n], end = rowptr[n + 1];
    int i = beg;
    for (; i + 4 <= end; i += 4) {
        int e0 = i + half, e1 = i + 2 + half;
        int   r0 = csr_src[e0],     r1 = csr_src[e1];
        float w0 = csr_w[e0] * dv,  w1 = csr_w[e1] * dv;
        uint4 u0 = ((const uint4*)(hWh + (size_t)r0 * H))[hl];
        uint4 u1 = ((const uint4*)(hWh + (size_t)r1 * H))[hl];
        float2 p;
        p = __half22float2(*(__half2*)&u0.x); acc[0] += p.x*w0; acc[1] += p.y*w0;
        p = __half22float2(*(__half2*)&u0.y); acc[2] += p.x*w0; acc[3] += p.y*w0;
        p = __half22float2(*(__half2*)&u0.z); acc[4] += p.x*w0; acc[5] += p.y*w0;
        p = __half22float2(*(__half2*)&u0.w); acc[6] += p.x*w0; acc[7] += p.y*w0;
        p = __half22float2(*(__half2*)&u1.x); acc[0] += p.x*w1; acc[1] += p.y*w1;
        p = __half22float2(*(__half2*)&u1.y); acc[2] += p.x*w1; acc[3] += p.y*w1;
        p = __half22float2(*(__half2*)&u1.z); acc[4] += p.x*w1; acc[5] += p.y*w1;
        p = __half22float2(*(__half2*)&u1.w); acc[6] += p.x*w1; acc[7] += p.y*w1;
    }
    for (; i < end; i += 2) {
        int e = i + half;
        int   r = n;
        float w = 0.f;
        if (e < end) { r = csr_src[e]; w = csr_w[e] * dv; }
        uint4 u = ((const uint4*)(hWh + (size_t)r * H))[hl];
        float2 p;
        p = __half22float2(*(__half2*)&u.x); acc[0] += p.x*w; acc[1] += p.y*w;
        p = __half22float2(*(__half2*)&u.y); acc[2] += p.x*w; acc[3] += p.y*w;
        p = __half22float2(*(__half2*)&u.z); acc[4] += p.x*w; acc[5] += p.y*w;
        p = __half22float2(*(__half2*)&u.w); acc[6] += p.x*w; acc[7] += p.y*w;
    }

#pragma unroll
    for (int f = 0; f < 8; f++)
        acc[f] += __shfl_xor_sync(0xffffffffu, acc[f], 16);

    if (half == 0) {
        float sn = dv * dv;
        uint4 us = ((const uint4*)(hWh + (size_t)n * H))[hl];
        float2 p;
        p = __half22float2(*(__half2*)&us.x); acc[0] += p.x*sn; acc[1] += p.y*sn;
        p = __half22float2(*(__half2*)&us.y); acc[2] += p.x*sn; acc[3] += p.y*sn;
        p = __half22float2(*(__half2*)&us.z); acc[4] += p.x*sn; acc[5] += p.y*sn;
        p = __half22float2(*(__half2*)&us.w); acc[6] += p.x*sn; acc[7] += p.y*sn;

        float4 b0 = ((const float4*)bias)[hl * 2];
        float4 b1 = ((const float4*)bias)[hl * 2 + 1];
        uint4 o;
        o.x = pack_h2(fmaxf(acc[0] + b0.x, 0.f), fmaxf(acc[1] + b0.y, 0.f));
        o.y = pack_h2(fmaxf(acc[2] + b0.z, 0.f), fmaxf(acc[3] + b0.w, 0.f));
        o.z = pack_h2(fmaxf(acc[4] + b1.x, 0.f), fmaxf(acc[5] + b1.y, 0.f));
        o.w = pack_h2(fmaxf(acc[6] + b1.z, 0.f), fmaxf(acc[7] + b1.w, 0.f));
        *(uint4*)(cath + (size_t)n * 384 + off + hl * 8) = o;
    }
}

// ---------------- final GEMM (fp16 mma): out = cat[N,384] @ Wlin[384,64] + blin ----------------
__global__ void __launch_bounds__(256) k_final_gemm(
    const __half* __restrict__ cath,
    const float* __restrict__ W,     // [384,64]
    const float* __restrict__ bias,  // [64]
    float* __restrict__ out, int N)
{
    __shared__ __half Xs[128][88];
    __shared__ __half Ws[64][72];

    const int tid  = threadIdx.x;
    const int lane = tid & 31;
    const int warp = tid >> 5;
    const int wm   = warp & 3;
    const int wn   = warp >> 2;
    const int row0 = blockIdx.x * 128;

    const int g  = lane >> 2;
    const int tg = lane & 3;

    float acc[2][4][4];
#pragma unroll
    for (int i = 0; i < 2; i++)
#pragma unroll
        for (int j = 0; j < 4; j++)
#pragma unroll
            for (int q = 0; q < 4; q++) acc[i][j][q] = 0.f;

    const int a_row = lane & 15;
    const int a_kof = (lane >> 4) * 8;
    const int b_krow = lane & 15;
    const int b_cof  = (lane >> 4) * 8;

    for (int kc = 0; kc < 384; kc += 64) {
        __syncthreads();
#pragma unroll
        for (int i = tid; i < 1024; i += 256) {
            int k = i >> 4, c4 = i & 15;
            float4 v = ((const float4*)(W + (size_t)(kc + k) * 64))[c4];
            uint2 p = make_uint2(pack_h2(v.x, v.y), pack_h2(v.z, v.w));
            *(uint2*)&Ws[k][c4 * 4] = p;
        }
#pragma unroll
        for (int i = tid; i < 1024; i += 256) {
            int r = i >> 3, c = i & 7;
            int gr = row0 + r;
            uint4 v = make_uint4(0u, 0u, 0u, 0u);
            if (gr < N) v = *(const uint4*)(cath + (size_t)gr * 384 + kc + c * 8);
            *(uint4*)&Xs[r][c * 8] = v;
        }
        __syncthreads();

#pragma unroll
        for (int kk = 0; kk < 4; kk++) {
            const int k0 = kk * 16;
            uint32_t a[2][4], b[4][2];
#pragma unroll
            for (int i = 0; i < 2; i++) {
                uint32_t ad = smem_u32(&Xs[wm * 32 + i * 16 + a_row][k0 + a_kof]);
                ldsm_x4(a[i], ad);
            }
#pragma unroll
            for (int jp = 0; jp < 2; jp++) {
                uint32_t r4[4];
                uint32_t ad = smem_u32(&Ws[k0 + b_krow][wn * 32 + jp * 16 + b_cof]);
                ldsm_x4_t(r4, ad);
                b[jp * 2    ][0] = r4[0]; b[jp * 2    ][1] = r4[1];
                b[jp * 2 + 1][0] = r4[2]; b[jp * 2 + 1][1] = r4[3];
            }
#pragma unroll
            for (int i = 0; i < 2; i++)
#pragma unroll
                for (int j = 0; j < 4; j++)
                    mma_f16(acc[i][j], a[i], b[j]);
        }
    }

#pragma unroll
    for (int i = 0; i < 2; i++) {
        int r = row0 + wm * 32 + i * 16 + g;
#pragma unroll
        for (int j = 0; j < 4; j++) {
            int c = wn * 32 + j * 8 + 2 * tg;
            float b0 = bias[c], b1 = bias[c + 1];
            if (r < N)
                *(float2*)(out + (size_t)r * 64 + c) =
                    make_float2(acc[i][j][0] + b0, acc[i][j][1] + b1);
            if (r + 8 < N)
                *(float2*)(out + (size_t)(r + 8) * 64 + c) =
                    make_float2(acc[i][j][2] + b0, acc[i][j][3] + b1);
        }
    }
}

// ---------------- launch ----------------
extern "C" void kernel_launch(void* const* d_in, const int* in_sizes, int n_in,
                              void* d_out, int out_size)
{
    const float* x    = (const float*)d_in[0];
    const int*   ei   = (const int*)d_in[1];      // int32 (JAX x64 disabled)
    const float* W1   = (const float*)d_in[2];
    const float* b1   = (const float*)d_in[3];
    const float* W2   = (const float*)d_in[4];
    const float* b2   = (const float*)d_in[5];
    const float* W3   = (const float*)d_in[6];
    const float* b3   = (const float*)d_in[7];
    const float* Wlin = (const float*)d_in[8];
    const float* blin = (const float*)d_in[9];
    float* out = (float*)d_out;

    float *dinv, *csr_w;
    __half *hWh, *cath;
    int *deg, *rowptr, *cursor, *bsums, *csr_src;
    cudaGetSymbolAddress((void**)&dinv,    g_dinv);
    cudaGetSymbolAddress((void**)&deg,     g_deg);
    cudaGetSymbolAddress((void**)&rowptr,  g_rowptr);
    cudaGetSymbolAddress((void**)&cursor,  g_cursor);
    cudaGetSymbolAddress((void**)&bsums,   g_bsums);
    cudaGetSymbolAddress((void**)&csr_src, g_csr_src);
    cudaGetSymbolAddress((void**)&csr_w,   g_csr_w);
    cudaGetSymbolAddress((void**)&hWh,     g_hWh);
    cudaGetSymbolAddress((void**)&cath,    g_cath);

    const int N = in_sizes[0] / H;      // 100000
    const int E = in_sizes[1] / 2;      // 1600000
    const int NB = (N + SCAN_CHUNK - 1) / SCAN_CHUNK;

    const int T = 256;
    const int gE    = (E + T - 1) / T;
    const int gGemm = (N + 127) / 128;
    const int gAgg  = (N + 7) / 8;

    // Fork a side stream so the CSR build (branch B) overlaps the layer-1
    // GEMM (branch A) inside the captured graph. Stream/event create+destroy
    // are host-side ops (no device allocs); destroy is deferred past enqueued
    // work on the eager correctness run.
    cudaStream_t s2;
    cudaStreamCreateWithFlags(&s2, cudaStreamNonBlocking);
    cudaEvent_t evFork, evJoin;
    cudaEventCreateWithFlags(&evFork, cudaEventDisableTiming);
    cudaEventCreateWithFlags(&evJoin, cudaEventDisableTiming);

    cudaEventRecord(evFork, 0);
    cudaStreamWaitEvent(s2, evFork, 0);

    // branch A (main stream): layer-1 GEMM
    k_conv_gemm<false><<<gGemm, T>>>(x, H, W1, hWh, N);

    // branch B (s2): CSR build
    cudaMemsetAsync(deg, 0, (size_t)N * sizeof(int), s2);
    k_hist <<<gE, T, 0, s2>>>(deg, ei, E);
    k_scan1<<<NB, SCAN_CHUNK, 0, s2>>>(deg, bsums, dinv, N);
    k_scan2<<<1, NB_MAX, 0, s2>>>(bsums, rowptr, NB, N);
    k_scan3<<<NB, SCAN_CHUNK, 0, s2>>>(deg, bsums, rowptr, cursor, N);
    k_fill <<<gE, T, 0, s2>>>(ei, dinv, cursor, csr_src, csr_w, E);

    // join
    cudaEventRecord(evJoin, s2);
    cudaStreamWaitEvent(0, evJoin, 0);

    // layer 1 aggregate
    k_aggregate<<<gAgg, T>>>(rowptr, csr_src, csr_w, dinv, hWh, b1, cath, 0, N);

    // layer 2
    k_conv_gemm<true><<<gGemm, T>>>(cath, 384, W2, hWh, N);
    k_aggregate<<<gAgg, T>>>(rowptr, csr_src, csr_w, dinv, hWh, b2, cath, 128, N);

    // layer 3
    k_conv_gemm<true><<<gGemm, T>>>(cath + 128, 384, W3, hWh, N);
    k_aggregate<<<gAgg, T>>>(rowptr, csr_src, csr_w, dinv, hWh, b3, cath, 256, N);

    // final
    k_final_gemm<<<gGemm, T>>>(cath, Wlin, blin, out, N);

    cudaEventDestroy(evFork);
    cudaEventDestroy(evJoin);
    cudaStreamDestroy(s2);
}